// round 14
// baseline (speedup 1.0000x reference)
#include <cuda_runtime.h>
#include <cuda_bf16.h>
#include <cstdint>

// ---------------------------------------------------------------------------
// Problem constants
// ---------------------------------------------------------------------------
#define BATCH 2
#define SEQ   2048
#define DMODEL 2048
#define KVD    512
#define NHEAD  16
#define NKVH   4
#define DHEAD  128
#define QKV_N   3072
#define KOFF    2048
#define VOFF    2560

// Scratch buffers (allocation-free rule: __device__ globals)
__device__ __nv_bfloat16 g_xb  [BATCH * SEQ * DMODEL];
__device__ __nv_bfloat16 g_QKVb[BATCH * SEQ * QKV_N];
__device__ __nv_bfloat16 g_Ob  [BATCH * SEQ * DMODEL];
__device__ __nv_bfloat16 g_Wcat[DMODEL * QKV_N];
__device__ __nv_bfloat16 g_Wob [DMODEL * DMODEL];

// work-queue state (reset in cvt_all each replay)
__device__ int g_ctr_qkv;
__device__ int g_ctr_flash;
__device__ int g_ctr_wo;
__device__ int g_done_qkv[32];      // [rb] -> qkv column tiles done (24 = ready)
__device__ int g_done[32];          // [b*16+qb] -> flash heads done (16 = ready)

__device__ __forceinline__ uint32_t packbf2(float lo, float hi) {
    __nv_bfloat162 h = __floats2bfloat162_rn(lo, hi);
    return *reinterpret_cast<uint32_t*>(&h);
}
__device__ __forceinline__ float2 unpkbf2(uint32_t u) {
    __nv_bfloat162 h = *reinterpret_cast<__nv_bfloat162*>(&u);
    return make_float2(__bfloat162float(h.x), __bfloat162float(h.y));
}
__device__ __forceinline__ uint32_t smem_u32(const void* p) {
    return (uint32_t)__cvta_generic_to_shared(p);
}
__device__ __forceinline__ void cp16(void* dst, const void* src) {
    asm volatile("cp.async.cg.shared.global [%0], [%1], 16;"
                 :: "r"(smem_u32(dst)), "l"(src));
}
#define CP_COMMIT() asm volatile("cp.async.commit_group;")
#define CP_WAIT1()  asm volatile("cp.async.wait_group 1;")
#define CP_WAIT0()  asm volatile("cp.async.wait_group 0;")

__device__ __forceinline__ void ldsm_x4(uint32_t r[4], uint32_t addr) {
    asm volatile("ldmatrix.sync.aligned.m8n8.x4.shared.b16 {%0,%1,%2,%3}, [%4];"
                 : "=r"(r[0]), "=r"(r[1]), "=r"(r[2]), "=r"(r[3]) : "r"(addr));
}
__device__ __forceinline__ void ldsm_x4_t(uint32_t r[4], uint32_t addr) {
    asm volatile("ldmatrix.sync.aligned.m8n8.x4.trans.shared.b16 {%0,%1,%2,%3}, [%4];"
                 : "=r"(r[0]), "=r"(r[1]), "=r"(r[2]), "=r"(r[3]) : "r"(addr));
}
__device__ __forceinline__ void mma_bf16(float c[4], const uint32_t a[4], const uint32_t b[2]) {
    asm volatile(
        "mma.sync.aligned.m16n8k16.row.col.f32.bf16.bf16.f32 "
        "{%0,%1,%2,%3}, {%4,%5,%6,%7}, {%8,%9}, {%0,%1,%2,%3};\n"
        : "+f"(c[0]), "+f"(c[1]), "+f"(c[2]), "+f"(c[3])
        : "r"(a[0]), "r"(a[1]), "r"(a[2]), "r"(a[3]),
          "r"(b[0]), "r"(b[1]));
}

// ---------------------------------------------------------------------------
// cvt_all: x->bf16, [Wq|Wk|Wv]->Wcat bf16, Wo->bf16; resets queue state.
// ---------------------------------------------------------------------------
#define NX4  (BATCH * SEQ * DMODEL / 4)
#define NW8  (DMODEL * QKV_N / 8)
#define NO4  (DMODEL * DMODEL / 4)
#define CVT_TOTAL (NX4 + NW8 + NO4)
#define CVT_BLOCKS ((CVT_TOTAL / 2 + 255) / 256)

__global__ __launch_bounds__(256)
void cvt_all(const float* __restrict__ x,
             const float* __restrict__ Wq, const float* __restrict__ Wk,
             const float* __restrict__ Wv, const float* __restrict__ Wo,
             __nv_bfloat16* __restrict__ xb, __nv_bfloat16* __restrict__ Wcat,
             __nv_bfloat16* __restrict__ Wob) {
    if (blockIdx.x == 0) {
        if (threadIdx.x < 32) { g_done[threadIdx.x] = 0; g_done_qkv[threadIdx.x] = 0; }
        else if (threadIdx.x == 32) g_ctr_flash = 0;
        else if (threadIdx.x == 33) g_ctr_wo = 0;
        else if (threadIdx.x == 34) g_ctr_qkv = 0;
    }
    const int stride = gridDim.x * blockDim.x;
    for (int i = blockIdx.x * blockDim.x + threadIdx.x; i < CVT_TOTAL; i += stride) {
        if (i < NX4) {
            const float4 v = ((const float4*)x)[i];
            uint32_t* d = (uint32_t*)xb + 2 * i;
            d[0] = packbf2(v.x, v.y); d[1] = packbf2(v.z, v.w);
        } else if (i < NX4 + NW8) {
            const int j = i - NX4;
            const int row = j / (QKV_N / 8);
            const int c8  = (j - row * (QKV_N / 8)) * 8;
            const float* src;
            if (c8 < KOFF)      src = Wq + (size_t)row * DMODEL + c8;
            else if (c8 < VOFF) src = Wk + (size_t)row * KVD + (c8 - KOFF);
            else                src = Wv + (size_t)row * KVD + (c8 - VOFF);
            const float4 a = *(const float4*)(src);
            const float4 b = *(const float4*)(src + 4);
            uint32_t* d = (uint32_t*)(Wcat + (size_t)row * QKV_N + c8);
            d[0] = packbf2(a.x, a.y); d[1] = packbf2(a.z, a.w);
            d[2] = packbf2(b.x, b.y); d[3] = packbf2(b.z, b.w);
        } else {
            const int j = i - NX4 - NW8;
            const float4 v = ((const float4*)Wo)[j];
            uint32_t* d = (uint32_t*)Wob + 2 * j;
            d[0] = packbf2(v.x, v.y); d[1] = packbf2(v.z, v.w);
        }
    }
}

// ---------------------------------------------------------------------------
// GEMM tile machinery (device functions used by the mega-kernel phases).
// CTA 128x128, 256 threads (8 warps 2x4), warp tile 64x32, BK=64, 3 stages.
// ---------------------------------------------------------------------------
#define AST 72
#define BST 136
#define A_STG (128 * AST)
#define B_STG (64 * BST)
#define STG_ELEMS (A_STG + B_STG)
#define GEMM_SMEM_BYTES (3 * STG_ELEMS * 2)   // 107520

// QKV tile with fused K-RMSNorm epilogue (K tiles: ct in [16,20)).
__device__ __forceinline__ void qkv_tile(
    int rb, int ct,
    const __nv_bfloat16* __restrict__ A,      // g_xb [4096][2048]
    const __nv_bfloat16* __restrict__ B,      // Wcat [2048][3072]
    const float* __restrict__ kg,
    __nv_bfloat16* __restrict__ Cb,           // g_QKVb
    __nv_bfloat16* smb) {
    __shared__ float sred[4][128];

    const int N = QKV_N, K = DMODEL;
    const int tid  = threadIdx.x;
    const int lane = tid & 31;
    const int wid  = tid >> 5;
    const int warpRow = wid & 1;
    const int warpCol = wid >> 1;
    const int grp = lane >> 2;
    const int tig = lane & 3;
    const size_t bm = (size_t)rb * 128;
    const size_t bn = (size_t)ct * 128;
    const int lrow = (lane & 7) + (lane & 8);
    const int lcol8 = ((lane >> 4) << 3);

    float acc[4][4][4];
    #pragma unroll
    for (int i = 0; i < 4; i++)
        #pragma unroll
        for (int j = 0; j < 4; j++)
            #pragma unroll
            for (int q = 0; q < 4; q++) acc[i][j][q] = 0.f;

    const int T = K / 64;

    auto issue = [&](int stage, int k0) {
        __nv_bfloat16* As = smb + stage * STG_ELEMS;
        __nv_bfloat16* Bs = As + A_STG;
        #pragma unroll
        for (int t = 0; t < 4; t++) {
            const int c = tid + t * 256;
            const int ar = c >> 3, akc = (c & 7) * 8;
            cp16(As + ar * AST + akc, A + (bm + ar) * K + k0 + akc);
            const int br = c >> 4, bnc = (c & 15) * 8;
            cp16(Bs + br * BST + bnc, B + (size_t)(k0 + br) * N + bn + bnc);
        }
        CP_COMMIT();
    };

    issue(0, 0);
    issue(1, 64);

    for (int i = 0; i < T; i++) {
        if (i + 1 < T) { CP_WAIT1(); } else { CP_WAIT0(); }
        __syncthreads();
        if (i + 2 < T) issue((i + 2) % 3, (i + 2) * 64);

        const __nv_bfloat16* As = smb + (i % 3) * STG_ELEMS;
        const __nv_bfloat16* Bs = As + A_STG;
        const uint32_t sA = smem_u32(As);
        const uint32_t sB = smem_u32(Bs);

        #pragma unroll
        for (int ks = 0; ks < 4; ks++) {
            uint32_t afr[4][4];
            #pragma unroll
            for (int mt = 0; mt < 4; mt++) {
                const int r = warpRow * 64 + mt * 16 + lrow;
                ldsm_x4(afr[mt], sA + (uint32_t)(r * AST + ks * 16 + lcol8) * 2);
            }
            uint32_t bfr[4][2];
            #pragma unroll
            for (int half = 0; half < 2; half++) {
                const int brow = ks * 16 + lrow;
                const int ncol = warpCol * 32 + half * 16 + lcol8;
                uint32_t rr[4];
                ldsm_x4_t(rr, sB + (uint32_t)(brow * BST + ncol) * 2);
                bfr[2 * half][0] = rr[0]; bfr[2 * half][1] = rr[1];
                bfr[2 * half + 1][0] = rr[2]; bfr[2 * half + 1][1] = rr[3];
            }
            #pragma unroll
            for (int mt = 0; mt < 4; mt++)
                #pragma unroll
                for (int nt = 0; nt < 4; nt++)
                    mma_bf16(acc[mt][nt], afr[mt], bfr[nt]);
        }
        __syncthreads();
    }

    // fused K-RMSNorm (tile == one K head)
    const bool isK = (ct >= 16) && (ct < 20);
    float rs[4][2];
    if (isK) {
        #pragma unroll
        for (int mt = 0; mt < 4; mt++) {
            float p0 = 0.f, p1 = 0.f;
            #pragma unroll
            for (int nt = 0; nt < 4; nt++) {
                p0 += acc[mt][nt][0] * acc[mt][nt][0] + acc[mt][nt][1] * acc[mt][nt][1];
                p1 += acc[mt][nt][2] * acc[mt][nt][2] + acc[mt][nt][3] * acc[mt][nt][3];
            }
            p0 += __shfl_xor_sync(0xffffffffu, p0, 1);
            p0 += __shfl_xor_sync(0xffffffffu, p0, 2);
            p1 += __shfl_xor_sync(0xffffffffu, p1, 1);
            p1 += __shfl_xor_sync(0xffffffffu, p1, 2);
            if (tig == 0) {
                const int r0 = warpRow * 64 + mt * 16 + grp;
                sred[warpCol][r0]     = p0;
                sred[warpCol][r0 + 8] = p1;
            }
        }
        __syncthreads();
        #pragma unroll
        for (int mt = 0; mt < 4; mt++) {
            const int r0 = warpRow * 64 + mt * 16 + grp;
            const float s0 = sred[0][r0] + sred[1][r0] + sred[2][r0] + sred[3][r0];
            const float s1 = sred[0][r0 + 8] + sred[1][r0 + 8] + sred[2][r0 + 8] + sred[3][r0 + 8];
            rs[mt][0] = rsqrtf(s0 * (1.0f / 128.0f) + 1e-8f);
            rs[mt][1] = rsqrtf(s1 * (1.0f / 128.0f) + 1e-8f);
        }
        __syncthreads();   // sred reusable
    }

    #pragma unroll
    for (int mt = 0; mt < 4; mt++) {
        #pragma unroll
        for (int nt = 0; nt < 4; nt++) {
            const int row = (int)bm + warpRow * 64 + mt * 16 + grp;
            const int col = (int)bn + warpCol * 32 + nt * 8 + 2 * tig;
            float a0 = acc[mt][nt][0], a1 = acc[mt][nt][1];
            float a2 = acc[mt][nt][2], a3 = acc[mt][nt][3];
            if (isK) {
                const float2 g = *(const float2*)(kg + warpCol * 32 + nt * 8 + 2 * tig);
                a0 *= rs[mt][0] * g.x; a1 *= rs[mt][0] * g.y;
                a2 *= rs[mt][1] * g.x; a3 *= rs[mt][1] * g.y;
            }
            *(uint32_t*)(Cb + (size_t)row * N + col) = packbf2(a0, a1);
            *(uint32_t*)(Cb + (size_t)(row + 8) * N + col) = packbf2(a2, a3);
        }
    }
}

// ---------------------------------------------------------------------------
// Flash attention item (BKV=128, fused Q-RMSNorm) — unchanged logic.
// ---------------------------------------------------------------------------
#define KV_ROW_U32 68
#define FSTAGE_U32 (2 * 128 * KV_ROW_U32)
#define FUSED_SMEM_BYTES (2 * FSTAGE_U32 * 4)      // 139264

__device__ __forceinline__ void flash_item(
    const __nv_bfloat16* __restrict__ QKV,
    const float* __restrict__ qgamma,
    __nv_bfloat16* __restrict__ Ob,
    int b, int h, int qb, uint32_t* smu) {

    const int kvh = h >> 2;
    const int tid  = threadIdx.x;
    const int lane = tid & 31;
    const int w    = tid >> 5;
    const int grp  = lane >> 2;
    const int tig  = lane & 3;
    const int q0   = qb * 128;
    const int lrow = (lane & 7) + (lane & 8);
    const int lcol8 = ((lane >> 4) << 3);
    const int kn_off = (lane & 7) + ((lane >> 4) << 3);
    const int kk_off = ((lane >> 3) & 1) * 8;

    const int r0g = q0 + w * 16 + grp;

    uint32_t qf[8][4];
    {
        const uint32_t* Qr  = (const uint32_t*)QKV + (size_t)(b * SEQ + r0g) * (QKV_N / 2) + h * (DHEAD / 2);
        const uint32_t* Qr8 = Qr + 8 * (size_t)(QKV_N / 2);
        #pragma unroll
        for (int kt = 0; kt < 8; kt++) {
            qf[kt][0] = Qr [kt * 8 + tig];
            qf[kt][1] = Qr8[kt * 8 + tig];
            qf[kt][2] = Qr [kt * 8 + tig + 4];
            qf[kt][3] = Qr8[kt * 8 + tig + 4];
        }
        float ss0 = 0.f, ss1 = 0.f;
        #pragma unroll
        for (int kt = 0; kt < 8; kt++) {
            const float2 a0 = unpkbf2(qf[kt][0]);
            const float2 a2 = unpkbf2(qf[kt][2]);
            ss0 += a0.x * a0.x + a0.y * a0.y + a2.x * a2.x + a2.y * a2.y;
            const float2 a1 = unpkbf2(qf[kt][1]);
            const float2 a3 = unpkbf2(qf[kt][3]);
            ss1 += a1.x * a1.x + a1.y * a1.y + a3.x * a3.x + a3.y * a3.y;
        }
        ss0 += __shfl_xor_sync(0xffffffffu, ss0, 1);
        ss0 += __shfl_xor_sync(0xffffffffu, ss0, 2);
        ss1 += __shfl_xor_sync(0xffffffffu, ss1, 1);
        ss1 += __shfl_xor_sync(0xffffffffu, ss1, 2);
        const float SCALE = 0.08838834764831845f;
        const float rs0 = rsqrtf(ss0 * (1.0f / 128.0f) + 1e-8f) * SCALE;
        const float rs1 = rsqrtf(ss1 * (1.0f / 128.0f) + 1e-8f) * SCALE;
        #pragma unroll
        for (int kt = 0; kt < 8; kt++) {
            const float2 g0 = *(const float2*)(qgamma + kt * 16 + 2 * tig);
            const float2 g8 = *(const float2*)(qgamma + kt * 16 + 8 + 2 * tig);
            float2 a;
            a = unpkbf2(qf[kt][0]); qf[kt][0] = packbf2(a.x * rs0 * g0.x, a.y * rs0 * g0.y);
            a = unpkbf2(qf[kt][1]); qf[kt][1] = packbf2(a.x * rs1 * g0.x, a.y * rs1 * g0.y);
            a = unpkbf2(qf[kt][2]); qf[kt][2] = packbf2(a.x * rs0 * g8.x, a.y * rs0 * g8.y);
            a = unpkbf2(qf[kt][3]); qf[kt][3] = packbf2(a.x * rs1 * g8.x, a.y * rs1 * g8.y);
        }
    }

    auto issue_tile = [&](int stage, int kv0) {
        uint32_t* Ks = smu + stage * FSTAGE_U32;
        uint32_t* Vs = Ks + 128 * KV_ROW_U32;
        const __nv_bfloat16* Kg = QKV + (size_t)(b * SEQ + kv0) * QKV_N + KOFF + kvh * DHEAD;
        const __nv_bfloat16* Vg = QKV + (size_t)(b * SEQ + kv0) * QKV_N + VOFF + kvh * DHEAD;
        #pragma unroll
        for (int t = 0; t < 8; t++) {
            const int c = tid + t * 256;
            const int row = c >> 4, ch = c & 15;
            cp16(Ks + row * KV_ROW_U32 + ch * 4, Kg + (size_t)row * QKV_N + ch * 8);
            cp16(Vs + row * KV_ROW_U32 + ch * 4, Vg + (size_t)row * QKV_N + ch * 8);
        }
        CP_COMMIT();
    };

    float oacc[16][4];
    #pragma unroll
    for (int i = 0; i < 16; i++)
        #pragma unroll
        for (int q = 0; q < 4; q++) oacc[i][q] = 0.f;
    float m0 = -1e30f, m1 = -1e30f, l0 = 0.f, l1 = 0.f;

    const int ntiles = qb + 1;
    issue_tile(0, 0);

    for (int t = 0; t < ntiles; t++) {
        const int kv0 = t * 128;
        CP_WAIT0();
        __syncthreads();
        if (t + 1 < ntiles) issue_tile((t + 1) & 1, (t + 1) * 128);

        const uint32_t* Ks = smu + (t & 1) * FSTAGE_U32;
        const uint32_t sK = smem_u32(Ks);
        const uint32_t sV = smem_u32(Ks + 128 * KV_ROW_U32);

        float s[16][4];
        #pragma unroll
        for (int nt = 0; nt < 16; nt++)
            #pragma unroll
            for (int q = 0; q < 4; q++) s[nt][q] = 0.f;

        #pragma unroll
        for (int kt = 0; kt < 8; kt++) {
            #pragma unroll
            for (int np = 0; np < 8; np++) {
                uint32_t rr[4];
                ldsm_x4(rr, sK + (uint32_t)((np * 16 + kn_off) * (KV_ROW_U32 * 4)
                                            + (kt * 16 + kk_off) * 2));
                mma_bf16(s[2 * np],     qf[kt], rr);
                mma_bf16(s[2 * np + 1], qf[kt], rr + 2);
            }
        }

        if (t == qb) {
            #pragma unroll
            for (int nt = 0; nt < 16; nt++) {
                const int col = kv0 + nt * 8 + 2 * tig;
                if (col     > r0g    ) s[nt][0] = -1e30f;
                if (col + 1 > r0g    ) s[nt][1] = -1e30f;
                if (col     > r0g + 8) s[nt][2] = -1e30f;
                if (col + 1 > r0g + 8) s[nt][3] = -1e30f;
            }
        }

        float mx0 = -1e30f, mx1 = -1e30f;
        #pragma unroll
        for (int nt = 0; nt < 16; nt++) {
            mx0 = fmaxf(mx0, fmaxf(s[nt][0], s[nt][1]));
            mx1 = fmaxf(mx1, fmaxf(s[nt][2], s[nt][3]));
        }
        mx0 = fmaxf(mx0, __shfl_xor_sync(0xffffffffu, mx0, 1));
        mx0 = fmaxf(mx0, __shfl_xor_sync(0xffffffffu, mx0, 2));
        mx1 = fmaxf(mx1, __shfl_xor_sync(0xffffffffu, mx1, 1));
        mx1 = fmaxf(mx1, __shfl_xor_sync(0xffffffffu, mx1, 2));

        const float mn0 = fmaxf(m0, mx0);
        const float mn1 = fmaxf(m1, mx1);
        const float al0 = __expf(m0 - mn0);
        const float al1 = __expf(m1 - mn1);

        float ls0 = 0.f, ls1 = 0.f;
        #pragma unroll
        for (int nt = 0; nt < 16; nt++) {
            s[nt][0] = __expf(s[nt][0] - mn0);
            s[nt][1] = __expf(s[nt][1] - mn0);
            s[nt][2] = __expf(s[nt][2] - mn1);
            s[nt][3] = __expf(s[nt][3] - mn1);
            ls0 += s[nt][0] + s[nt][1];
            ls1 += s[nt][2] + s[nt][3];
        }
        ls0 += __shfl_xor_sync(0xffffffffu, ls0, 1);
        ls0 += __shfl_xor_sync(0xffffffffu, ls0, 2);
        ls1 += __shfl_xor_sync(0xffffffffu, ls1, 1);
        ls1 += __shfl_xor_sync(0xffffffffu, ls1, 2);
        l0 = l0 * al0 + ls0;  m0 = mn0;
        l1 = l1 * al1 + ls1;  m1 = mn1;

        #pragma unroll
        for (int nt = 0; nt < 16; nt++) {
            oacc[nt][0] *= al0; oacc[nt][1] *= al0;
            oacc[nt][2] *= al1; oacc[nt][3] *= al1;
        }

        #pragma unroll
        for (int kc = 0; kc < 8; kc++) {
            uint32_t af[4];
            af[0] = packbf2(s[2 * kc][0],     s[2 * kc][1]);
            af[1] = packbf2(s[2 * kc][2],     s[2 * kc][3]);
            af[2] = packbf2(s[2 * kc + 1][0], s[2 * kc + 1][1]);
            af[3] = packbf2(s[2 * kc + 1][2], s[2 * kc + 1][3]);
            #pragma unroll
            for (int nblk = 0; nblk < 8; nblk++) {
                uint32_t rr[4];
                ldsm_x4_t(rr, sV + (uint32_t)((kc * 16 + lrow) * (KV_ROW_U32 * 4)
                                              + (nblk * 16 + lcol8) * 2));
                mma_bf16(oacc[2 * nblk],     af, rr);
                mma_bf16(oacc[2 * nblk + 1], af, rr + 2);
            }
        }
    }

    const float i0 = 1.0f / l0;
    const float i1 = 1.0f / l1;
    __nv_bfloat16* Og  = Ob + ((size_t)(b * SEQ + r0g) * DMODEL) + h * DHEAD;
    __nv_bfloat16* Og8 = Og + 8 * (size_t)DMODEL;
    #pragma unroll
    for (int nt = 0; nt < 16; nt++) {
        const int col = nt * 8 + 2 * tig;
        *(uint32_t*)(Og  + col) = packbf2(oacc[nt][0] * i0, oacc[nt][1] * i0);
        *(uint32_t*)(Og8 + col) = packbf2(oacc[nt][2] * i1, oacc[nt][3] * i1);
    }
}

// ---------------------------------------------------------------------------
// Wo tile (fp32 out + residual) — unchanged logic.
// ---------------------------------------------------------------------------
__device__ __forceinline__ void wo_tile(
    int rt, int ct,
    const __nv_bfloat16* __restrict__ A,
    const __nv_bfloat16* __restrict__ B,
    const float* __restrict__ R, float* __restrict__ C,
    __nv_bfloat16* smb) {

    const int N = DMODEL, K = DMODEL;
    const int tid  = threadIdx.x;
    const int lane = tid & 31;
    const int wid  = tid >> 5;
    const int warpRow = wid & 1;
    const int warpCol = wid >> 1;
    const int grp = lane >> 2;
    const int tig = lane & 3;
    const size_t bm = (size_t)rt * 128;
    const size_t bn = (size_t)ct * 128;
    const int lrow = (lane & 7) + (lane & 8);
    const int lcol8 = ((lane >> 4) << 3);

    float acc[4][4][4];
    #pragma unroll
    for (int i = 0; i < 4; i++)
        #pragma unroll
        for (int j = 0; j < 4; j++)
            #pragma unroll
            for (int q = 0; q < 4; q++) acc[i][j][q] = 0.f;

    const int T = K / 64;

    auto issue = [&](int stage, int k0) {
        __nv_bfloat16* As = smb + stage * STG_ELEMS;
        __nv_bfloat16* Bs = As + A_STG;
        #pragma unroll
        for (int t = 0; t < 4; t++) {
            const int c = tid + t * 256;
            const int ar = c >> 3, akc = (c & 7) * 8;
            cp16(As + ar * AST + akc, A + (bm + ar) * K + k0 + akc);
            const int br = c >> 4, bnc = (c & 15) * 8;
            cp16(Bs + br * BST + bnc, B + (size_t)(k0 + br) * N + bn + bnc);
        }
        CP_COMMIT();
    };

    issue(0, 0);
    issue(1, 64);

    for (int i = 0; i < T; i++) {
        if (i + 1 < T) { CP_WAIT1(); } else { CP_WAIT0(); }
        __syncthreads();
        if (i + 2 < T) issue((i + 2) % 3, (i + 2) * 64);

        const __nv_bfloat16* As = smb + (i % 3) * STG_ELEMS;
        const __nv_bfloat16* Bs = As + A_STG;
        const uint32_t sA = smem_u32(As);
        const uint32_t sB = smem_u32(Bs);

        #pragma unroll
        for (int ks = 0; ks < 4; ks++) {
            uint32_t afr[4][4];
            #pragma unroll
            for (int mt = 0; mt < 4; mt++) {
                const int r = warpRow * 64 + mt * 16 + lrow;
                ldsm_x4(afr[mt], sA + (uint32_t)(r * AST + ks * 16 + lcol8) * 2);
            }
            uint32_t bfr[4][2];
            #pragma unroll
            for (int half = 0; half < 2; half++) {
                const int brow = ks * 16 + lrow;
                const int ncol = warpCol * 32 + half * 16 + lcol8;
                uint32_t rr[4];
                ldsm_x4_t(rr, sB + (uint32_t)(brow * BST + ncol) * 2);
                bfr[2 * half][0] = rr[0]; bfr[2 * half][1] = rr[1];
                bfr[2 * half + 1][0] = rr[2]; bfr[2 * half + 1][1] = rr[3];
            }
            #pragma unroll
            for (int mt = 0; mt < 4; mt++)
                #pragma unroll
                for (int nt = 0; nt < 4; nt++)
                    mma_bf16(acc[mt][nt], afr[mt], bfr[nt]);
        }
        __syncthreads();
    }

    #pragma unroll
    for (int mt = 0; mt < 4; mt++) {
        #pragma unroll
        for (int nt = 0; nt < 4; nt++) {
            const int row = (int)bm + warpRow * 64 + mt * 16 + grp;
            const int col = (int)bn + warpCol * 32 + nt * 8 + 2 * tig;
            float2 v0 = make_float2(acc[mt][nt][0], acc[mt][nt][1]);
            float2 v1 = make_float2(acc[mt][nt][2], acc[mt][nt][3]);
            const float2 r0 = *(const float2*)(R + (size_t)row * N + col);
            const float2 r1 = *(const float2*)(R + (size_t)(row + 8) * N + col);
            v0.x += r0.x; v0.y += r0.y;
            v1.x += r1.x; v1.y += r1.y;
            *(float2*)(C + (size_t)row * N + col) = v0;
            *(float2*)(C + (size_t)(row + 8) * N + col) = v1;
        }
    }
}

// ---------------------------------------------------------------------------
// Mega persistent kernel: QKV tiles -> flash items -> Wo tiles, work queues.
// ---------------------------------------------------------------------------
__global__ __launch_bounds__(256, 1)
void mega(const __nv_bfloat16* __restrict__ xb,
          const __nv_bfloat16* __restrict__ Wcat,
          const float* __restrict__ kgamma,
          __nv_bfloat16* __restrict__ QKV,
          const float* __restrict__ qgamma,
          __nv_bfloat16* __restrict__ Ob,
          const float* __restrict__ x,
          const __nv_bfloat16* __restrict__ Wob,
          float* __restrict__ out) {
    extern __shared__ uint32_t smu[];
    __shared__ int s_it;

    // ---- Phase A: QKV tiles (row-blocks ascending -> unlock flash early) ----
    for (;;) {
        __syncthreads();
        if (threadIdx.x == 0) s_it = atomicAdd(&g_ctr_qkv, 1);
        __syncthreads();
        const int it = s_it;
        if (it >= 768) break;
        const int rb = it / 24;
        const int ct = it - rb * 24;
        qkv_tile(rb, ct, xb, Wcat, kgamma, QKV, (__nv_bfloat16*)smu);
        __threadfence();
        __syncthreads();
        if (threadIdx.x == 0) atomicAdd(&g_done_qkv[rb], 1);
    }

    // ---- Phase B: flash items (ascending qb: earliest-unlocked first) ----
    for (;;) {
        __syncthreads();
        if (threadIdx.x == 0) s_it = atomicAdd(&g_ctr_flash, 1);
        __syncthreads();
        const int it = s_it;
        if (it >= 512) break;
        const int qb = it >> 5;
        const int h  = it & 15;
        const int b  = (it >> 4) & 1;
        if (threadIdx.x == 0) {
            for (int qb2 = 0; qb2 <= qb; qb2++) {
                while (atomicAdd(&g_done_qkv[b * 16 + qb2], 0) < 24) { }
            }
        }
        __syncthreads();
        flash_item(QKV, qgamma, Ob, b, h, qb, smu);
        __threadfence();
        __syncthreads();
        if (threadIdx.x == 0) atomicAdd(&g_done[b * 16 + qb], 1);
    }

    // ---- Phase C: Wo tiles (ascending qb, matching flash completion) ----
    for (;;) {
        __syncthreads();
        if (threadIdx.x == 0) s_it = atomicAdd(&g_ctr_wo, 1);
        __syncthreads();
        const int it = s_it;
        if (it >= 512) break;
        const int qi = it >> 4;
        const int ct = it & 15;
        const int qb = qi >> 1;
        const int b  = qi & 1;
        const int rt = b * 16 + qb;
        if (threadIdx.x == 0) {
            while (atomicAdd(&g_done[rt], 0) < 16) { }
        }
        __syncthreads();
        wo_tile(rt, ct, Ob, Wob, x, out, (__nv_bfloat16*)smu);
    }
}

// ---------------------------------------------------------------------------
// launch
// ---------------------------------------------------------------------------
extern "C" void kernel_launch(void* const* d_in, const int* in_sizes, int n_in,
                              void* d_out, int out_size) {
    const float* x  = (const float*)d_in[0];
    const float* Wq = (const float*)d_in[1];
    const float* Wk = (const float*)d_in[2];
    const float* Wv = (const float*)d_in[3];
    const float* Wo = (const float*)d_in[4];
    const float* qg = (const float*)d_in[5];
    const float* kg = (const float*)d_in[6];
    float* out = (float*)d_out;

    __nv_bfloat16 *pxb, *pQKV, *pOb, *pWcat, *pWob;
    cudaGetSymbolAddress((void**)&pxb,  g_xb);
    cudaGetSymbolAddress((void**)&pQKV, g_QKVb);
    cudaGetSymbolAddress((void**)&pOb,  g_Ob);
    cudaGetSymbolAddress((void**)&pWcat, g_Wcat);
    cudaGetSymbolAddress((void**)&pWob,  g_Wob);

    // 1) conversions + queue reset
    cvt_all<<<CVT_BLOCKS, 256>>>(x, Wq, Wk, Wv, Wo, pxb, pWcat, pWob);

    // 2) persistent mega-kernel: QKV -> flash -> Wo with dependency gating
    cudaFuncSetAttribute(mega, cudaFuncAttributeMaxDynamicSharedMemorySize,
                         FUSED_SMEM_BYTES);
    mega<<<152, 256, FUSED_SMEM_BYTES>>>(pxb, pWcat, kg, pQKV, qg, pOb, x, pWob, out);
}

// round 15
// speedup vs baseline: 1.0701x; 1.0701x over previous
#include <cuda_runtime.h>
#include <cuda_bf16.h>
#include <cstdint>

// ---------------------------------------------------------------------------
// Problem constants
// ---------------------------------------------------------------------------
#define BATCH 2
#define SEQ   2048
#define DMODEL 2048
#define KVD    512
#define NHEAD  16
#define NKVH   4
#define DHEAD  128
#define QKV_N   3072
#define KOFF    2048
#define VOFF    2560

// Scratch buffers (allocation-free rule: __device__ globals)
__device__ __nv_bfloat16 g_xb  [BATCH * SEQ * DMODEL];
__device__ __nv_bfloat16 g_QKVb[BATCH * SEQ * QKV_N];
__device__ __nv_bfloat16 g_Ob  [BATCH * SEQ * DMODEL];
__device__ __nv_bfloat16 g_Wcat[DMODEL * QKV_N];
__device__ __nv_bfloat16 g_Wob [DMODEL * DMODEL];

// work-queue state for the fused attention+Wo kernel (reset in cvt_all)
__device__ int g_ctr_flash;
__device__ int g_ctr_wo;
__device__ int g_done[32];          // [b*16+qb] -> heads completed (16 = ready)

__device__ __forceinline__ uint32_t packbf2(float lo, float hi) {
    __nv_bfloat162 h = __floats2bfloat162_rn(lo, hi);
    return *reinterpret_cast<uint32_t*>(&h);
}
__device__ __forceinline__ float2 unpkbf2(uint32_t u) {
    __nv_bfloat162 h = *reinterpret_cast<__nv_bfloat162*>(&u);
    return make_float2(__bfloat162float(h.x), __bfloat162float(h.y));
}
__device__ __forceinline__ uint32_t smem_u32(const void* p) {
    return (uint32_t)__cvta_generic_to_shared(p);
}
__device__ __forceinline__ void cp16(void* dst, const void* src) {
    asm volatile("cp.async.cg.shared.global [%0], [%1], 16;"
                 :: "r"(smem_u32(dst)), "l"(src));
}
#define CP_COMMIT() asm volatile("cp.async.commit_group;")
#define CP_WAIT1()  asm volatile("cp.async.wait_group 1;")
#define CP_WAIT0()  asm volatile("cp.async.wait_group 0;")

__device__ __forceinline__ void ldsm_x4(uint32_t r[4], uint32_t addr) {
    asm volatile("ldmatrix.sync.aligned.m8n8.x4.shared.b16 {%0,%1,%2,%3}, [%4];"
                 : "=r"(r[0]), "=r"(r[1]), "=r"(r[2]), "=r"(r[3]) : "r"(addr));
}
__device__ __forceinline__ void ldsm_x4_t(uint32_t r[4], uint32_t addr) {
    asm volatile("ldmatrix.sync.aligned.m8n8.x4.trans.shared.b16 {%0,%1,%2,%3}, [%4];"
                 : "=r"(r[0]), "=r"(r[1]), "=r"(r[2]), "=r"(r[3]) : "r"(addr));
}
__device__ __forceinline__ void mma_bf16(float c[4], const uint32_t a[4], const uint32_t b[2]) {
    asm volatile(
        "mma.sync.aligned.m16n8k16.row.col.f32.bf16.bf16.f32 "
        "{%0,%1,%2,%3}, {%4,%5,%6,%7}, {%8,%9}, {%0,%1,%2,%3};\n"
        : "+f"(c[0]), "+f"(c[1]), "+f"(c[2]), "+f"(c[3])
        : "r"(a[0]), "r"(a[1]), "r"(a[2]), "r"(a[3]),
          "r"(b[0]), "r"(b[1]));
}

// ---------------------------------------------------------------------------
// cvt_all: x->bf16, [Wq|Wk|Wv]->Wcat bf16, Wo->bf16; resets queue state.
// Grid-stride x2 (latency-bound kernel).
// ---------------------------------------------------------------------------
#define NX4  (BATCH * SEQ * DMODEL / 4)
#define NW8  (DMODEL * QKV_N / 8)
#define NO4  (DMODEL * DMODEL / 4)
#define CVT_TOTAL (NX4 + NW8 + NO4)
#define CVT_BLOCKS ((CVT_TOTAL / 2 + 255) / 256)

__global__ __launch_bounds__(256)
void cvt_all(const float* __restrict__ x,
             const float* __restrict__ Wq, const float* __restrict__ Wk,
             const float* __restrict__ Wv, const float* __restrict__ Wo,
             __nv_bfloat16* __restrict__ xb, __nv_bfloat16* __restrict__ Wcat,
             __nv_bfloat16* __restrict__ Wob) {
    if (blockIdx.x == 0 && threadIdx.x < 34) {
        if (threadIdx.x == 32)      g_ctr_flash = 0;
        else if (threadIdx.x == 33) g_ctr_wo = 0;
        else                        g_done[threadIdx.x] = 0;
    }
    const int stride = gridDim.x * blockDim.x;
    for (int i = blockIdx.x * blockDim.x + threadIdx.x; i < CVT_TOTAL; i += stride) {
        if (i < NX4) {
            const float4 v = ((const float4*)x)[i];
            uint32_t* d = (uint32_t*)xb + 2 * i;
            d[0] = packbf2(v.x, v.y); d[1] = packbf2(v.z, v.w);
        } else if (i < NX4 + NW8) {
            const int j = i - NX4;
            const int row = j / (QKV_N / 8);
            const int c8  = (j - row * (QKV_N / 8)) * 8;
            const float* src;
            if (c8 < KOFF)      src = Wq + (size_t)row * DMODEL + c8;
            else if (c8 < VOFF) src = Wk + (size_t)row * KVD + (c8 - KOFF);
            else                src = Wv + (size_t)row * KVD + (c8 - VOFF);
            const float4 a = *(const float4*)(src);
            const float4 b = *(const float4*)(src + 4);
            uint32_t* d = (uint32_t*)(Wcat + (size_t)row * QKV_N + c8);
            d[0] = packbf2(a.x, a.y); d[1] = packbf2(a.z, a.w);
            d[2] = packbf2(b.x, b.y); d[3] = packbf2(b.z, b.w);
        } else {
            const int j = i - NX4 - NW8;
            const float4 v = ((const float4*)Wo)[j];
            uint32_t* d = (uint32_t*)Wob + 2 * j;
            d[0] = packbf2(v.x, v.y); d[1] = packbf2(v.z, v.w);
        }
    }
}

// ---------------------------------------------------------------------------
// QKV GEMM (standalone, occ 2 — measured best config).
// CTA 128x128, 256 threads (8 warps 2x4), warp tile 64x32, BK=64, 3 stages.
// ---------------------------------------------------------------------------
#define AST 72
#define BST 136
#define A_STG (128 * AST)
#define B_STG (64 * BST)
#define STG_ELEMS (A_STG + B_STG)
#define GEMM_SMEM_BYTES (3 * STG_ELEMS * 2)

__global__ __launch_bounds__(256, 2)
void gemm_qkv(int M, int N, int K,
              const __nv_bfloat16* __restrict__ A,
              const __nv_bfloat16* __restrict__ B,
              __nv_bfloat16* __restrict__ Cb) {
    extern __shared__ __nv_bfloat16 smb[];

    const int tid  = threadIdx.x;
    const int lane = tid & 31;
    const int wid  = tid >> 5;
    const int warpRow = wid & 1;
    const int warpCol = wid >> 1;
    const int grp = lane >> 2;
    const int tig = lane & 3;
    const size_t bm = (size_t)blockIdx.y * 128;
    const size_t bn = (size_t)blockIdx.x * 128;
    const int lrow = (lane & 7) + (lane & 8);
    const int lcol8 = ((lane >> 4) << 3);

    float acc[4][4][4];
    #pragma unroll
    for (int i = 0; i < 4; i++)
        #pragma unroll
        for (int j = 0; j < 4; j++)
            #pragma unroll
            for (int q = 0; q < 4; q++) acc[i][j][q] = 0.f;

    const int T = K / 64;

    auto issue = [&](int stage, int k0) {
        __nv_bfloat16* As = smb + stage * STG_ELEMS;
        __nv_bfloat16* Bs = As + A_STG;
        #pragma unroll
        for (int t = 0; t < 4; t++) {
            const int c = tid + t * 256;
            const int ar = c >> 3, akc = (c & 7) * 8;
            cp16(As + ar * AST + akc, A + (bm + ar) * K + k0 + akc);
            const int br = c >> 4, bnc = (c & 15) * 8;
            cp16(Bs + br * BST + bnc, B + (size_t)(k0 + br) * N + bn + bnc);
        }
        CP_COMMIT();
    };

    issue(0, 0);
    issue(1, 64);

    for (int i = 0; i < T; i++) {
        if (i + 1 < T) { CP_WAIT1(); } else { CP_WAIT0(); }
        __syncthreads();
        if (i + 2 < T) issue((i + 2) % 3, (i + 2) * 64);

        const __nv_bfloat16* As = smb + (i % 3) * STG_ELEMS;
        const __nv_bfloat16* Bs = As + A_STG;
        const uint32_t sA = smem_u32(As);
        const uint32_t sB = smem_u32(Bs);

        #pragma unroll
        for (int ks = 0; ks < 4; ks++) {
            uint32_t afr[4][4];
            #pragma unroll
            for (int mt = 0; mt < 4; mt++) {
                const int r = warpRow * 64 + mt * 16 + lrow;
                ldsm_x4(afr[mt], sA + (uint32_t)(r * AST + ks * 16 + lcol8) * 2);
            }
            uint32_t bfr[4][2];
            #pragma unroll
            for (int half = 0; half < 2; half++) {
                const int brow = ks * 16 + lrow;
                const int ncol = warpCol * 32 + half * 16 + lcol8;
                uint32_t rr[4];
                ldsm_x4_t(rr, sB + (uint32_t)(brow * BST + ncol) * 2);
                bfr[2 * half][0] = rr[0]; bfr[2 * half][1] = rr[1];
                bfr[2 * half + 1][0] = rr[2]; bfr[2 * half + 1][1] = rr[3];
            }
            #pragma unroll
            for (int mt = 0; mt < 4; mt++)
                #pragma unroll
                for (int nt = 0; nt < 4; nt++)
                    mma_bf16(acc[mt][nt], afr[mt], bfr[nt]);
        }
        __syncthreads();
    }

    #pragma unroll
    for (int mt = 0; mt < 4; mt++) {
        #pragma unroll
        for (int nt = 0; nt < 4; nt++) {
            const int row = (int)bm + warpRow * 64 + mt * 16 + grp;
            const int col = (int)bn + warpCol * 32 + nt * 8 + 2 * tig;
            *(uint32_t*)(Cb + (size_t)row * N + col) =
                packbf2(acc[mt][nt][0], acc[mt][nt][1]);
            *(uint32_t*)(Cb + (size_t)(row + 8) * N + col) =
                packbf2(acc[mt][nt][2], acc[mt][nt][3]);
        }
    }
}

// ---------------------------------------------------------------------------
// RMSNorm for K heads (separate kernel — measured best).
// ---------------------------------------------------------------------------
__global__ __launch_bounds__(256)
void rmsnorm_k(__nv_bfloat16* __restrict__ t, const float* __restrict__ kg) {
    const int w = (blockIdx.x * blockDim.x + threadIdx.x) >> 5;
    const int NK = BATCH * SEQ * NKVH;
    if (w >= NK) return;
    const int lane = threadIdx.x & 31;
    const size_t off = (size_t)(w >> 2) * QKV_N + KOFF + (w & 3) * DHEAD;
    uint2* p = (uint2*)(t + off) + lane;
    uint2 v = *p;
    const float2 a = unpkbf2(v.x);
    const float2 b = unpkbf2(v.y);
    float ss = a.x * a.x + a.y * a.y + b.x * b.x + b.y * b.y;
    #pragma unroll
    for (int o = 16; o; o >>= 1) ss += __shfl_xor_sync(0xffffffffu, ss, o);
    const float rs = rsqrtf(ss * (1.0f / 128.0f) + 1e-8f);
    const float4 gg = ((const float4*)kg)[lane];
    v.x = packbf2(a.x * rs * gg.x, a.y * rs * gg.y);
    v.y = packbf2(b.x * rs * gg.z, b.y * rs * gg.w);
    *p = v;
}

// ---------------------------------------------------------------------------
// Fused attention + Wo persistent kernel.
// Phase 1: flash items (BKV=128, fused Q-RMSNorm), heavy qb first.
// Phase 2: Wo tiles 128x256 (64x64 warp tile — high ILP for occ-1), gated.
// ---------------------------------------------------------------------------
#define KV_ROW_U32 68
#define FSTAGE_U32 (2 * 128 * KV_ROW_U32)
#define FUSED_SMEM_BYTES (2 * FSTAGE_U32 * 4)      // 139264

__device__ __forceinline__ void flash_item(
    const __nv_bfloat16* __restrict__ QKV,
    const float* __restrict__ qgamma,
    __nv_bfloat16* __restrict__ Ob,
    int b, int h, int qb, uint32_t* smu) {

    const int kvh = h >> 2;
    const int tid  = threadIdx.x;
    const int lane = tid & 31;
    const int w    = tid >> 5;
    const int grp  = lane >> 2;
    const int tig  = lane & 3;
    const int q0   = qb * 128;
    const int lrow = (lane & 7) + (lane & 8);
    const int lcol8 = ((lane >> 4) << 3);
    const int kn_off = (lane & 7) + ((lane >> 4) << 3);
    const int kk_off = ((lane >> 3) & 1) * 8;

    const int r0g = q0 + w * 16 + grp;

    uint32_t qf[8][4];
    {
        const uint32_t* Qr  = (const uint32_t*)QKV + (size_t)(b * SEQ + r0g) * (QKV_N / 2) + h * (DHEAD / 2);
        const uint32_t* Qr8 = Qr + 8 * (size_t)(QKV_N / 2);
        #pragma unroll
        for (int kt = 0; kt < 8; kt++) {
            qf[kt][0] = Qr [kt * 8 + tig];
            qf[kt][1] = Qr8[kt * 8 + tig];
            qf[kt][2] = Qr [kt * 8 + tig + 4];
            qf[kt][3] = Qr8[kt * 8 + tig + 4];
        }
        float ss0 = 0.f, ss1 = 0.f;
        #pragma unroll
        for (int kt = 0; kt < 8; kt++) {
            const float2 a0 = unpkbf2(qf[kt][0]);
            const float2 a2 = unpkbf2(qf[kt][2]);
            ss0 += a0.x * a0.x + a0.y * a0.y + a2.x * a2.x + a2.y * a2.y;
            const float2 a1 = unpkbf2(qf[kt][1]);
            const float2 a3 = unpkbf2(qf[kt][3]);
            ss1 += a1.x * a1.x + a1.y * a1.y + a3.x * a3.x + a3.y * a3.y;
        }
        ss0 += __shfl_xor_sync(0xffffffffu, ss0, 1);
        ss0 += __shfl_xor_sync(0xffffffffu, ss0, 2);
        ss1 += __shfl_xor_sync(0xffffffffu, ss1, 1);
        ss1 += __shfl_xor_sync(0xffffffffu, ss1, 2);
        const float SCALE = 0.08838834764831845f;
        const float rs0 = rsqrtf(ss0 * (1.0f / 128.0f) + 1e-8f) * SCALE;
        const float rs1 = rsqrtf(ss1 * (1.0f / 128.0f) + 1e-8f) * SCALE;
        #pragma unroll
        for (int kt = 0; kt < 8; kt++) {
            const float2 g0 = *(const float2*)(qgamma + kt * 16 + 2 * tig);
            const float2 g8 = *(const float2*)(qgamma + kt * 16 + 8 + 2 * tig);
            float2 a;
            a = unpkbf2(qf[kt][0]); qf[kt][0] = packbf2(a.x * rs0 * g0.x, a.y * rs0 * g0.y);
            a = unpkbf2(qf[kt][1]); qf[kt][1] = packbf2(a.x * rs1 * g0.x, a.y * rs1 * g0.y);
            a = unpkbf2(qf[kt][2]); qf[kt][2] = packbf2(a.x * rs0 * g8.x, a.y * rs0 * g8.y);
            a = unpkbf2(qf[kt][3]); qf[kt][3] = packbf2(a.x * rs1 * g8.x, a.y * rs1 * g8.y);
        }
    }

    auto issue_tile = [&](int stage, int kv0) {
        uint32_t* Ks = smu + stage * FSTAGE_U32;
        uint32_t* Vs = Ks + 128 * KV_ROW_U32;
        const __nv_bfloat16* Kg = QKV + (size_t)(b * SEQ + kv0) * QKV_N + KOFF + kvh * DHEAD;
        const __nv_bfloat16* Vg = QKV + (size_t)(b * SEQ + kv0) * QKV_N + VOFF + kvh * DHEAD;
        #pragma unroll
        for (int t = 0; t < 8; t++) {
            const int c = tid + t * 256;
            const int row = c >> 4, ch = c & 15;
            cp16(Ks + row * KV_ROW_U32 + ch * 4, Kg + (size_t)row * QKV_N + ch * 8);
            cp16(Vs + row * KV_ROW_U32 + ch * 4, Vg + (size_t)row * QKV_N + ch * 8);
        }
        CP_COMMIT();
    };

    float oacc[16][4];
    #pragma unroll
    for (int i = 0; i < 16; i++)
        #pragma unroll
        for (int q = 0; q < 4; q++) oacc[i][q] = 0.f;
    float m0 = -1e30f, m1 = -1e30f, l0 = 0.f, l1 = 0.f;

    const int ntiles = qb + 1;
    issue_tile(0, 0);

    for (int t = 0; t < ntiles; t++) {
        const int kv0 = t * 128;
        CP_WAIT0();
        __syncthreads();
        if (t + 1 < ntiles) issue_tile((t + 1) & 1, (t + 1) * 128);

        const uint32_t* Ks = smu + (t & 1) * FSTAGE_U32;
        const uint32_t sK = smem_u32(Ks);
        const uint32_t sV = smem_u32(Ks + 128 * KV_ROW_U32);

        float s[16][4];
        #pragma unroll
        for (int nt = 0; nt < 16; nt++)
            #pragma unroll
            for (int q = 0; q < 4; q++) s[nt][q] = 0.f;

        #pragma unroll
        for (int kt = 0; kt < 8; kt++) {
            #pragma unroll
            for (int np = 0; np < 8; np++) {
                uint32_t rr[4];
                ldsm_x4(rr, sK + (uint32_t)((np * 16 + kn_off) * (KV_ROW_U32 * 4)
                                            + (kt * 16 + kk_off) * 2));
                mma_bf16(s[2 * np],     qf[kt], rr);
                mma_bf16(s[2 * np + 1], qf[kt], rr + 2);
            }
        }

        if (t == qb) {
            #pragma unroll
            for (int nt = 0; nt < 16; nt++) {
                const int col = kv0 + nt * 8 + 2 * tig;
                if (col     > r0g    ) s[nt][0] = -1e30f;
                if (col + 1 > r0g    ) s[nt][1] = -1e30f;
                if (col     > r0g + 8) s[nt][2] = -1e30f;
                if (col + 1 > r0g + 8) s[nt][3] = -1e30f;
            }
        }

        float mx0 = -1e30f, mx1 = -1e30f;
        #pragma unroll
        for (int nt = 0; nt < 16; nt++) {
            mx0 = fmaxf(mx0, fmaxf(s[nt][0], s[nt][1]));
            mx1 = fmaxf(mx1, fmaxf(s[nt][2], s[nt][3]));
        }
        mx0 = fmaxf(mx0, __shfl_xor_sync(0xffffffffu, mx0, 1));
        mx0 = fmaxf(mx0, __shfl_xor_sync(0xffffffffu, mx0, 2));
        mx1 = fmaxf(mx1, __shfl_xor_sync(0xffffffffu, mx1, 1));
        mx1 = fmaxf(mx1, __shfl_xor_sync(0xffffffffu, mx1, 2));

        const float mn0 = fmaxf(m0, mx0);
        const float mn1 = fmaxf(m1, mx1);
        const float al0 = __expf(m0 - mn0);
        const float al1 = __expf(m1 - mn1);

        float ls0 = 0.f, ls1 = 0.f;
        #pragma unroll
        for (int nt = 0; nt < 16; nt++) {
            s[nt][0] = __expf(s[nt][0] - mn0);
            s[nt][1] = __expf(s[nt][1] - mn0);
            s[nt][2] = __expf(s[nt][2] - mn1);
            s[nt][3] = __expf(s[nt][3] - mn1);
            ls0 += s[nt][0] + s[nt][1];
            ls1 += s[nt][2] + s[nt][3];
        }
        ls0 += __shfl_xor_sync(0xffffffffu, ls0, 1);
        ls0 += __shfl_xor_sync(0xffffffffu, ls0, 2);
        ls1 += __shfl_xor_sync(0xffffffffu, ls1, 1);
        ls1 += __shfl_xor_sync(0xffffffffu, ls1, 2);
        l0 = l0 * al0 + ls0;  m0 = mn0;
        l1 = l1 * al1 + ls1;  m1 = mn1;

        #pragma unroll
        for (int nt = 0; nt < 16; nt++) {
            oacc[nt][0] *= al0; oacc[nt][1] *= al0;
            oacc[nt][2] *= al1; oacc[nt][3] *= al1;
        }

        #pragma unroll
        for (int kc = 0; kc < 8; kc++) {
            uint32_t af[4];
            af[0] = packbf2(s[2 * kc][0],     s[2 * kc][1]);
            af[1] = packbf2(s[2 * kc][2],     s[2 * kc][3]);
            af[2] = packbf2(s[2 * kc + 1][0], s[2 * kc + 1][1]);
            af[3] = packbf2(s[2 * kc + 1][2], s[2 * kc + 1][3]);
            #pragma unroll
            for (int nblk = 0; nblk < 8; nblk++) {
                uint32_t rr[4];
                ldsm_x4_t(rr, sV + (uint32_t)((kc * 16 + lrow) * (KV_ROW_U32 * 4)
                                              + (nblk * 16 + lcol8) * 2));
                mma_bf16(oacc[2 * nblk],     af, rr);
                mma_bf16(oacc[2 * nblk + 1], af, rr + 2);
            }
        }
    }

    const float i0 = 1.0f / l0;
    const float i1 = 1.0f / l1;
    __nv_bfloat16* Og  = Ob + ((size_t)(b * SEQ + r0g) * DMODEL) + h * DHEAD;
    __nv_bfloat16* Og8 = Og + 8 * (size_t)DMODEL;
    #pragma unroll
    for (int nt = 0; nt < 16; nt++) {
        const int col = nt * 8 + 2 * tig;
        *(uint32_t*)(Og  + col) = packbf2(oacc[nt][0] * i0, oacc[nt][1] * i0);
        *(uint32_t*)(Og8 + col) = packbf2(oacc[nt][2] * i1, oacc[nt][3] * i1);
    }
}

// ---------------------------------------------------------------------------
// Wo tile v2: 128x256 CTA tile, warp tile 64x64 (2x4 warp grid), BK=64,
// 2-stage pipeline. High per-warp ILP for the occ-1 persistent kernel.
// smem/stage: A[128][72] + B[64][264] = 26112 bf16 -> 2 stages = 104448 B.
// ---------------------------------------------------------------------------
#define WBST 264
#define WB_STG (64 * WBST)
#define WSTG_ELEMS (A_STG + WB_STG)   // 26112

__device__ __forceinline__ void wo_tile(
    int rt, int ct,
    const __nv_bfloat16* __restrict__ A,       // g_Ob [4096][2048]
    const __nv_bfloat16* __restrict__ B,       // Wob  [2048][2048]
    const float* __restrict__ R, float* __restrict__ C,
    __nv_bfloat16* smb) {

    const int N = DMODEL, K = DMODEL;
    const int tid  = threadIdx.x;
    const int lane = tid & 31;
    const int wid  = tid >> 5;
    const int warpRow = wid & 1;       // 0..1 -> 64 rows
    const int warpCol = wid >> 1;      // 0..3 -> 64 cols
    const int grp = lane >> 2;
    const int tig = lane & 3;
    const size_t bm = (size_t)rt * 128;
    const size_t bn = (size_t)ct * 256;
    const int lrow = (lane & 7) + (lane & 8);
    const int lcol8 = ((lane >> 4) << 3);

    float acc[4][8][4];
    #pragma unroll
    for (int i = 0; i < 4; i++)
        #pragma unroll
        for (int j = 0; j < 8; j++)
            #pragma unroll
            for (int q = 0; q < 4; q++) acc[i][j][q] = 0.f;

    const int T = K / 64;   // 32

    auto issue = [&](int stage, int k0) {
        __nv_bfloat16* As = smb + stage * WSTG_ELEMS;
        __nv_bfloat16* Bs = As + A_STG;
        #pragma unroll
        for (int t = 0; t < 4; t++) {
            const int c = tid + t * 256;                 // A: 1024 chunks
            const int ar = c >> 3, akc = (c & 7) * 8;
            cp16(As + ar * AST + akc, A + (bm + ar) * K + k0 + akc);
        }
        #pragma unroll
        for (int t = 0; t < 8; t++) {
            const int c = tid + t * 256;                 // B: 2048 chunks
            const int br = c >> 5, bnc = (c & 31) * 8;
            cp16(Bs + br * WBST + bnc, B + (size_t)(k0 + br) * N + bn + bnc);
        }
        CP_COMMIT();
    };

    issue(0, 0);

    for (int i = 0; i < T; i++) {
        if (i + 1 < T) { issue((i + 1) & 1, (i + 1) * 64); CP_WAIT1(); }
        else           { CP_WAIT0(); }
        __syncthreads();

        const __nv_bfloat16* As = smb + (i & 1) * WSTG_ELEMS;
        const __nv_bfloat16* Bs = As + A_STG;
        const uint32_t sA = smem_u32(As);
        const uint32_t sB = smem_u32(Bs);

        #pragma unroll
        for (int ks = 0; ks < 4; ks++) {
            uint32_t afr[4][4];
            #pragma unroll
            for (int mt = 0; mt < 4; mt++) {
                const int r = warpRow * 64 + mt * 16 + lrow;
                ldsm_x4(afr[mt], sA + (uint32_t)(r * AST + ks * 16 + lcol8) * 2);
            }
            #pragma unroll
            for (int half = 0; half < 4; half++) {
                const int brow = ks * 16 + lrow;
                const int ncol = warpCol * 64 + half * 16 + lcol8;
                uint32_t rr[4];
                ldsm_x4_t(rr, sB + (uint32_t)(brow * WBST + ncol) * 2);
                #pragma unroll
                for (int mt = 0; mt < 4; mt++) {
                    mma_bf16(acc[mt][2 * half],     afr[mt], rr);
                    mma_bf16(acc[mt][2 * half + 1], afr[mt], rr + 2);
                }
            }
        }
        __syncthreads();
    }

    #pragma unroll
    for (int mt = 0; mt < 4; mt++) {
        #pragma unroll
        for (int nt = 0; nt < 8; nt++) {
            const int row = (int)bm + warpRow * 64 + mt * 16 + grp;
            const int col = (int)bn + warpCol * 64 + nt * 8 + 2 * tig;
            float2 v0 = make_float2(acc[mt][nt][0], acc[mt][nt][1]);
            float2 v1 = make_float2(acc[mt][nt][2], acc[mt][nt][3]);
            const float2 r0 = *(const float2*)(R + (size_t)row * N + col);
            const float2 r1 = *(const float2*)(R + (size_t)(row + 8) * N + col);
            v0.x += r0.x; v0.y += r0.y;
            v1.x += r1.x; v1.y += r1.y;
            *(float2*)(C + (size_t)row * N + col) = v0;
            *(float2*)(C + (size_t)(row + 8) * N + col) = v1;
        }
    }
}

__global__ __launch_bounds__(256, 1)
void fused_attn_wo(const __nv_bfloat16* __restrict__ QKV,
                   const float* __restrict__ qgamma,
                   __nv_bfloat16* __restrict__ Ob,
                   const float* __restrict__ x,
                   const __nv_bfloat16* __restrict__ Wob,
                   float* __restrict__ out) {
    extern __shared__ uint32_t smu[];
    __shared__ int s_it;

    // ---- Phase 1: flash attention items (heavy qb first) ----
    for (;;) {
        __syncthreads();
        if (threadIdx.x == 0) s_it = atomicAdd(&g_ctr_flash, 1);
        __syncthreads();
        const int it = s_it;
        if (it >= 512) break;
        const int qb = 15 - (it >> 5);
        const int h  = it & 15;
        const int b  = (it >> 4) & 1;
        flash_item(QKV, qgamma, Ob, b, h, qb, smu);
        __threadfence();
        __syncthreads();
        if (threadIdx.x == 0) atomicAdd(&g_done[b * 16 + qb], 1);
    }

    // ---- Phase 2: Wo tiles (128x256), gated on row-block readiness ----
    for (;;) {
        __syncthreads();
        if (threadIdx.x == 0) s_it = atomicAdd(&g_ctr_wo, 1);
        __syncthreads();
        const int it = s_it;
        if (it >= 256) break;
        const int qi = it >> 3;                 // readiness order: qb desc
        const int ct = it & 7;
        const int qb = 15 - (qi >> 1);
        const int b  = qi & 1;
        const int rt = b * 16 + qb;
        if (threadIdx.x == 0) {
            while (atomicAdd(&g_done[rt], 0) < 16) { }
        }
        __syncthreads();
        wo_tile(rt, ct, Ob, Wob, x, out, (__nv_bfloat16*)smu);
    }
}

// ---------------------------------------------------------------------------
// launch
// ---------------------------------------------------------------------------
extern "C" void kernel_launch(void* const* d_in, const int* in_sizes, int n_in,
                              void* d_out, int out_size) {
    const float* x  = (const float*)d_in[0];
    const float* Wq = (const float*)d_in[1];
    const float* Wk = (const float*)d_in[2];
    const float* Wv = (const float*)d_in[3];
    const float* Wo = (const float*)d_in[4];
    const float* qg = (const float*)d_in[5];
    const float* kg = (const float*)d_in[6];
    float* out = (float*)d_out;

    __nv_bfloat16 *pxb, *pQKV, *pOb, *pWcat, *pWob;
    cudaGetSymbolAddress((void**)&pxb,  g_xb);
    cudaGetSymbolAddress((void**)&pQKV, g_QKVb);
    cudaGetSymbolAddress((void**)&pOb,  g_Ob);
    cudaGetSymbolAddress((void**)&pWcat, g_Wcat);
    cudaGetSymbolAddress((void**)&pWob,  g_Wob);

    const int M = BATCH * SEQ;  // 4096

    // 1) conversions + queue-counter reset
    cvt_all<<<CVT_BLOCKS, 256>>>(x, Wq, Wk, Wv, Wo, pxb, pWcat, pWob);

    // 2) fused QKV projection (bf16 out, occ 2)
    cudaFuncSetAttribute(gemm_qkv, cudaFuncAttributeMaxDynamicSharedMemorySize,
                         GEMM_SMEM_BYTES);
    gemm_qkv<<<dim3(QKV_N / 128, M / 128), 256, GEMM_SMEM_BYTES>>>(
        M, QKV_N, DMODEL, pxb, pWcat, pQKV);

    // 3) K RMSNorm
    rmsnorm_k<<<(M * NKVH + 7) / 8, 256>>>(pQKV, kg);

    // 4) fused flash attention + Wo projection (persistent, work queues)
    cudaFuncSetAttribute(fused_attn_wo, cudaFuncAttributeMaxDynamicSharedMemorySize,
                         FUSED_SMEM_BYTES);
    fused_attn_wo<<<152, 256, FUSED_SMEM_BYTES>>>(pQKV, qg, pOb, x, pWob, out);
}